// round 15
// baseline (speedup 1.0000x reference)
#include <cuda_runtime.h>
#include <cuda_bf16.h>
#include <cstdint>

#define N_NODES 50000
#define N_EDGES 600000
#define D_FEAT  128
#define OUT_DIM 128
#define K_DIM   256

#define SCAN_BLK 512
#define N_SCAN_BLKS ((N_NODES + SCAN_BLK - 1) / SCAN_BLK)   // 98

// ---------------------------------------------------------------------------
// Scratch (static device globals)
// ---------------------------------------------------------------------------
__device__ int g_cnt_i [N_NODES];
__device__ int g_off   [N_NODES];
__device__ int g_btot  [N_SCAN_BLKS];
__device__ __align__(16) int g_rank[N_EDGES];
__device__ int g_eid   [N_EDGES];
__device__ __align__(16) float g_agg[N_NODES * D_FEAT];   // 25.6 MB

// ---------------------------------------------------------------------------
// Kernel: zero counters
// ---------------------------------------------------------------------------
__global__ void zero_counters_kernel() {
    int i = blockIdx.x * blockDim.x + threadIdx.x;
    if (i < N_NODES) g_cnt_i[i] = 0;
}

// ---------------------------------------------------------------------------
// Kernel: histogram + per-edge rank, 4 edges per thread
// ---------------------------------------------------------------------------
__global__ void count_rank_kernel(const int* __restrict__ src_idx) {
    const int t = blockIdx.x * blockDim.x + threadIdx.x;
    const int e = t * 4;
    if (e >= N_EDGES) return;
    const int4 s = *reinterpret_cast<const int4*>(src_idx + e);
    int4 r;
    r.x = atomicAdd(&g_cnt_i[s.x], 1);
    r.y = atomicAdd(&g_cnt_i[s.y], 1);
    r.z = atomicAdd(&g_cnt_i[s.z], 1);
    r.w = atomicAdd(&g_cnt_i[s.w], 1);
    *reinterpret_cast<int4*>(g_rank + e) = r;
}

// ---------------------------------------------------------------------------
// Kernel: per-block exclusive scan (warp-shuffle, 2 barriers)
// ---------------------------------------------------------------------------
__global__ __launch_bounds__(SCAN_BLK)
void scan_partial_kernel() {
    __shared__ int wtot[16];
    const int tid  = threadIdx.x;
    const int lane = tid & 31;
    const int wid  = tid >> 5;
    const int i    = blockIdx.x * SCAN_BLK + tid;
    const int v    = (i < N_NODES) ? g_cnt_i[i] : 0;

    int x = v;
    #pragma unroll
    for (int d = 1; d < 32; d <<= 1) {
        int y = __shfl_up_sync(0xffffffffu, x, d);
        if (lane >= d) x += y;
    }
    if (lane == 31) wtot[wid] = x;
    __syncthreads();

    if (wid == 0) {
        int w = (lane < 16) ? wtot[lane] : 0;
        int ws = w;
        #pragma unroll
        for (int d = 1; d < 16; d <<= 1) {
            int y = __shfl_up_sync(0xffffffffu, ws, d);
            if (lane >= d) ws += y;
        }
        if (lane < 16) wtot[lane] = ws - w;
    }
    __syncthreads();

    const int incl = x + wtot[wid];
    if (i < N_NODES) g_off[i] = incl - v;
    if (tid == SCAN_BLK - 1) g_btot[blockIdx.x] = incl;
}

// ---------------------------------------------------------------------------
// Inline 98-element exclusive prefix of g_btot. All threads join.
// ---------------------------------------------------------------------------
__device__ __forceinline__ void boff_scan(int* sb) {
    const int tid = threadIdx.x;
    int v = 0;
    if (tid < 128) {
        v = (tid < N_SCAN_BLKS) ? g_btot[tid] : 0;
        sb[tid] = v;
    }
    __syncthreads();
    #pragma unroll
    for (int d = 1; d < 128; d <<= 1) {
        int x = (tid < 128 && tid >= d) ? sb[tid - d] : 0;
        __syncthreads();
        if (tid < 128) sb[tid] += x;
        __syncthreads();
    }
    if (tid < 128) sb[tid] -= v;
    __syncthreads();
}

// ---------------------------------------------------------------------------
// Kernel: scatter edge ids — atomic-free, 4 edges per thread
// ---------------------------------------------------------------------------
__global__ __launch_bounds__(256)
void scatter_ids_kernel(const int* __restrict__ src_idx) {
    __shared__ int sb[128];
    boff_scan(sb);
    const int t = blockIdx.x * blockDim.x + threadIdx.x;
    const int e = t * 4;
    if (e >= N_EDGES) return;
    const int4 s = *reinterpret_cast<const int4*>(src_idx + e);
    const int4 r = *reinterpret_cast<const int4*>(g_rank + e);
    g_eid[g_off[s.x] + sb[s.x >> 9] + r.x] = e;
    g_eid[g_off[s.y] + sb[s.y >> 9] + r.y] = e + 1;
    g_eid[g_off[s.z] + sb[s.z >> 9] + r.z] = e + 2;
    g_eid[g_off[s.w] + sb[s.w >> 9] + r.w] = e + 3;
}

// ---------------------------------------------------------------------------
// Kernel: gather-reduce (proven). One warp per node; 4 edge rows in flight.
// Runs ALONE (full occupancy envelope) — fusion/overlap with it always lost.
// ---------------------------------------------------------------------------
__global__ __launch_bounds__(256)
void gather_kernel(const float* __restrict__ nbr_feat) {
    __shared__ int sb[128];
    boff_scan(sb);

    const int warp = (blockIdx.x * blockDim.x + threadIdx.x) >> 5;
    const int lane = threadIdx.x & 31;
    if (warp >= N_NODES) return;

    const int base = g_off[warp] + sb[warp >> 9];
    const int deg  = g_cnt_i[warp];

    const float4* nb4 = reinterpret_cast<const float4*>(nbr_feat);
    float4 acc = make_float4(0.f, 0.f, 0.f, 0.f);

    int i = 0;
    for (; i + 4 <= deg; i += 4) {
        const int e0 = g_eid[base + i];
        const int e1 = g_eid[base + i + 1];
        const int e2 = g_eid[base + i + 2];
        const int e3 = g_eid[base + i + 3];
        const float4 v0 = nb4[(size_t)e0 * (D_FEAT / 4) + lane];
        const float4 v1 = nb4[(size_t)e1 * (D_FEAT / 4) + lane];
        const float4 v2 = nb4[(size_t)e2 * (D_FEAT / 4) + lane];
        const float4 v3 = nb4[(size_t)e3 * (D_FEAT / 4) + lane];
        acc.x += (v0.x + v1.x) + (v2.x + v3.x);
        acc.y += (v0.y + v1.y) + (v2.y + v3.y);
        acc.z += (v0.z + v1.z) + (v2.z + v3.z);
        acc.w += (v0.w + v1.w) + (v2.w + v3.w);
    }
    for (; i < deg; ++i) {
        const int e = g_eid[base + i];
        const float4 v = nb4[(size_t)e * (D_FEAT / 4) + lane];
        acc.x += v.x; acc.y += v.y; acc.z += v.z; acc.w += v.w;
    }

    const float s = (deg > 0) ? (1.0f / (float)deg) : 0.0f;
    acc.x *= s; acc.y *= s; acc.z *= s; acc.w *= s;
    reinterpret_cast<float4*>(g_agg)[(size_t)warp * (D_FEAT / 4) + lane] = acc;
}

// ---------------------------------------------------------------------------
// GEMM half tile (proven R10 inner loop — do NOT touch: smem-dup (R11) and
// 4x8 retile (R12) both regressed). 64 rows x 128 cols, K=128, smem 96KB,
// 2 CTAs/SM, 8x4 thread tile, fma.rn.f32x2.
// (256,2) = 128-reg budget (NEVER lower: (256,4) spilled, +50us).
// ---------------------------------------------------------------------------
#define BM   64
#define TPB  256
#define KH   128
#define GEMM_SMEM ((KH * OUT_DIM + BM * KH) * 4)    // 98304 B

__device__ __forceinline__ void gemm_half(const float* __restrict__ xsrc,
                                          const float* __restrict__ Wh,
                                          float*       __restrict__ out,
                                          int n0, float* sh, bool addout) {
    float* Wsh = sh;                 // [KH][OUT_DIM]
    float* Xsh = sh + KH * OUT_DIM;  // [BM][KH]
    const int tid = threadIdx.x;

    {
        const float4* W4 = reinterpret_cast<const float4*>(Wh);
        float4* Wsh4 = reinterpret_cast<float4*>(Wsh);
        #pragma unroll
        for (int i = tid; i < KH * OUT_DIM / 4; i += TPB) Wsh4[i] = W4[i];
    }
    {
        const float4* x4 = reinterpret_cast<const float4*>(xsrc);
        const float4  z  = make_float4(0.f, 0.f, 0.f, 0.f);
        #pragma unroll
        for (int i = tid; i < BM * (KH / 4); i += TPB) {
            const int r  = i / (KH / 4);
            const int c4 = i % (KH / 4);
            const int n  = n0 + r;
            float4 v = z;
            if (n < N_NODES) v = x4[(size_t)n * (D_FEAT / 4) + c4];
            reinterpret_cast<float4*>(&Xsh[r * KH])[c4] = v;
        }
    }
    __syncthreads();

    const int j0 = (tid & 31) * 4;
    const int r0 = (tid >> 5) * 8;

    unsigned long long a01[8], a23[8];
    #pragma unroll
    for (int r = 0; r < 8; ++r) { a01[r] = 0ull; a23[r] = 0ull; }

    #pragma unroll 2
    for (int k = 0; k < KH; k += 2) {
        const unsigned long long wA0 =
            *reinterpret_cast<const unsigned long long*>(&Wsh[k * OUT_DIM + j0]);
        const unsigned long long wB0 =
            *reinterpret_cast<const unsigned long long*>(&Wsh[k * OUT_DIM + j0 + 2]);
        const unsigned long long wA1 =
            *reinterpret_cast<const unsigned long long*>(&Wsh[(k + 1) * OUT_DIM + j0]);
        const unsigned long long wB1 =
            *reinterpret_cast<const unsigned long long*>(&Wsh[(k + 1) * OUT_DIM + j0 + 2]);

        #pragma unroll
        for (int r = 0; r < 8; ++r) {
            const float2 x = *reinterpret_cast<const float2*>(&Xsh[(r0 + r) * KH + k]);
            unsigned long long xx0, xx1;
            asm("mov.b64 %0, {%1, %1};" : "=l"(xx0) : "f"(x.x));
            asm("mov.b64 %0, {%1, %1};" : "=l"(xx1) : "f"(x.y));
            asm("fma.rn.f32x2 %0, %1, %2, %0;" : "+l"(a01[r]) : "l"(xx0), "l"(wA0));
            asm("fma.rn.f32x2 %0, %1, %2, %0;" : "+l"(a23[r]) : "l"(xx0), "l"(wB0));
            asm("fma.rn.f32x2 %0, %1, %2, %0;" : "+l"(a01[r]) : "l"(xx1), "l"(wA1));
            asm("fma.rn.f32x2 %0, %1, %2, %0;" : "+l"(a23[r]) : "l"(xx1), "l"(wB1));
        }
    }

    #pragma unroll
    for (int r = 0; r < 8; ++r) {
        const int n = n0 + r0 + r;
        if (n < N_NODES) {
            float o0, o1, o2, o3;
            asm("mov.b64 {%0, %1}, %2;" : "=f"(o0), "=f"(o1) : "l"(a01[r]));
            asm("mov.b64 {%0, %1}, %2;" : "=f"(o2), "=f"(o3) : "l"(a23[r]));
            float4* po = reinterpret_cast<float4*>(&out[(size_t)n * OUT_DIM + j0]);
            if (addout) {
                const float4 p = *po;
                *po = make_float4(p.x + o0, p.y + o1, p.z + o2, p.w + o3);
            } else {
                *po = make_float4(o0, o1, o2, o3);
            }
        }
    }
}

// half0: out = self_feat @ W[0:128)  — independent of sort/gather
__global__ __launch_bounds__(TPB, 2)
void gemm_half0_kernel(const float* __restrict__ self_feat,
                       const float* __restrict__ W,
                       float*       __restrict__ out) {
    extern __shared__ float sh[];
    gemm_half(self_feat, W, out, blockIdx.x * BM, sh, /*addout=*/false);
}

// half1: out += g_agg @ W[128:256)
__global__ __launch_bounds__(TPB, 2)
void gemm_half1_kernel(const float* __restrict__ W,
                       float*       __restrict__ out) {
    extern __shared__ float sh[];
    gemm_half(g_agg, W + KH * OUT_DIM, out, blockIdx.x * BM, sh, /*addout=*/true);
}

// ---------------------------------------------------------------------------
// Launch. gemm_half0 forks onto stream 2 and JOINS BEFORE GATHER: it overlaps
// only the sort phase (latency-bound, low-issue, ~0 smem — complementary
// resources). The gather and gemm_half1 each run alone with full envelopes.
// (R9 failed because gemm0 overlapped the gather; R13 because the gather was
// trapped inside the GEMM envelope. This keeps both lessons.)
// ---------------------------------------------------------------------------
extern "C" void kernel_launch(void* const* d_in, const int* in_sizes, int n_in,
                              void* d_out, int out_size) {
    const float* self_feat = (const float*)d_in[0];
    const float* nbr_feat  = (const float*)d_in[1];
    const int*   src_idx   = (const int*)  d_in[2];
    const float* W         = (const float*)d_in[3];
    float*       out       = (float*)d_out;

    (void)in_sizes; (void)n_in; (void)out_size;

    // Lazily-created host objects (no device memory).
    static cudaStream_t s2 = nullptr;
    static cudaEvent_t ev_fork = nullptr, ev_join = nullptr;
    if (s2 == nullptr) {
        cudaStreamCreateWithFlags(&s2, cudaStreamNonBlocking);
        cudaEventCreateWithFlags(&ev_fork, cudaEventDisableTiming);
        cudaEventCreateWithFlags(&ev_join, cudaEventDisableTiming);
    }

    const int nodes_blks = (N_NODES + 255) / 256;
    const int e4_blks    = (N_EDGES / 4 + 255) / 256;

    cudaFuncSetAttribute(gemm_half0_kernel,
                         cudaFuncAttributeMaxDynamicSharedMemorySize, GEMM_SMEM);
    cudaFuncSetAttribute(gemm_half1_kernel,
                         cudaFuncAttributeMaxDynamicSharedMemorySize, GEMM_SMEM);

    // Fork: gemm_half0 on s2
    cudaEventRecord(ev_fork, 0);
    cudaStreamWaitEvent(s2, ev_fork, 0);
    gemm_half0_kernel<<<(N_NODES + BM - 1) / BM, TPB, GEMM_SMEM, s2>>>(
        self_feat, W, out);
    cudaEventRecord(ev_join, s2);

    // Sort phase on the capture stream (overlaps gemm_half0)
    zero_counters_kernel<<<nodes_blks, 256>>>();
    count_rank_kernel<<<e4_blks, 256>>>(src_idx);
    scan_partial_kernel<<<N_SCAN_BLKS, SCAN_BLK>>>();
    scatter_ids_kernel<<<e4_blks, 256>>>(src_idx);

    // Join BEFORE gather — gather must run with the whole chip to itself
    cudaStreamWaitEvent(0, ev_join, 0);
    gather_kernel<<<(N_NODES + 7) / 8, 256>>>(nbr_feat);

    gemm_half1_kernel<<<(N_NODES + BM - 1) / BM, TPB, GEMM_SMEM>>>(W, out);
}

// round 16
// speedup vs baseline: 1.1248x; 1.1248x over previous
#include <cuda_runtime.h>
#include <cuda_bf16.h>
#include <cstdint>

#define N_NODES 50000
#define N_EDGES 600000
#define D_FEAT  128
#define OUT_DIM 128
#define K_DIM   256

#define SCAN_BLK 512
#define N_SCAN_BLKS ((N_NODES + SCAN_BLK - 1) / SCAN_BLK)   // 98

// ---------------------------------------------------------------------------
// Scratch (static device globals)
// ---------------------------------------------------------------------------
__device__ int g_cnt_i [N_NODES];
__device__ int g_off   [N_NODES];
__device__ int g_btot  [N_SCAN_BLKS];
__device__ __align__(16) int g_rank[N_EDGES];
__device__ int g_eid   [N_EDGES];
__device__ __align__(16) float g_agg[N_NODES * D_FEAT];   // 25.6 MB

// ---------------------------------------------------------------------------
// Kernel: zero counters
// ---------------------------------------------------------------------------
__global__ void zero_counters_kernel() {
    int i = blockIdx.x * blockDim.x + threadIdx.x;
    if (i < N_NODES) g_cnt_i[i] = 0;
}

// ---------------------------------------------------------------------------
// Kernel: histogram + per-edge rank, 4 edges per thread
// ---------------------------------------------------------------------------
__global__ void count_rank_kernel(const int* __restrict__ src_idx) {
    const int t = blockIdx.x * blockDim.x + threadIdx.x;
    const int e = t * 4;
    if (e >= N_EDGES) return;
    const int4 s = *reinterpret_cast<const int4*>(src_idx + e);
    int4 r;
    r.x = atomicAdd(&g_cnt_i[s.x], 1);
    r.y = atomicAdd(&g_cnt_i[s.y], 1);
    r.z = atomicAdd(&g_cnt_i[s.z], 1);
    r.w = atomicAdd(&g_cnt_i[s.w], 1);
    *reinterpret_cast<int4*>(g_rank + e) = r;
}

// ---------------------------------------------------------------------------
// Kernel: per-block exclusive scan (warp-shuffle)
// ---------------------------------------------------------------------------
__global__ __launch_bounds__(SCAN_BLK)
void scan_partial_kernel() {
    __shared__ int wtot[16];
    const int tid  = threadIdx.x;
    const int lane = tid & 31;
    const int wid  = tid >> 5;
    const int i    = blockIdx.x * SCAN_BLK + tid;
    const int v    = (i < N_NODES) ? g_cnt_i[i] : 0;

    int x = v;
    #pragma unroll
    for (int d = 1; d < 32; d <<= 1) {
        int y = __shfl_up_sync(0xffffffffu, x, d);
        if (lane >= d) x += y;
    }
    if (lane == 31) wtot[wid] = x;
    __syncthreads();

    if (wid == 0) {
        int w = (lane < 16) ? wtot[lane] : 0;
        int ws = w;
        #pragma unroll
        for (int d = 1; d < 16; d <<= 1) {
            int y = __shfl_up_sync(0xffffffffu, ws, d);
            if (lane >= d) ws += y;
        }
        if (lane < 16) wtot[lane] = ws - w;
    }
    __syncthreads();

    const int incl = x + wtot[wid];
    if (i < N_NODES) g_off[i] = incl - v;
    if (tid == SCAN_BLK - 1) g_btot[blockIdx.x] = incl;
}

// ---------------------------------------------------------------------------
// Inline 98-element exclusive prefix of g_btot. All threads join.
// ---------------------------------------------------------------------------
__device__ __forceinline__ void boff_scan(int* sb) {
    const int tid = threadIdx.x;
    int v = 0;
    if (tid < 128) {
        v = (tid < N_SCAN_BLKS) ? g_btot[tid] : 0;
        sb[tid] = v;
    }
    __syncthreads();
    #pragma unroll
    for (int d = 1; d < 128; d <<= 1) {
        int x = (tid < 128 && tid >= d) ? sb[tid - d] : 0;
        __syncthreads();
        if (tid < 128) sb[tid] += x;
        __syncthreads();
    }
    if (tid < 128) sb[tid] -= v;
    __syncthreads();
}

// ---------------------------------------------------------------------------
// Kernel: scatter edge ids — atomic-free, 4 edges per thread
// ---------------------------------------------------------------------------
__global__ __launch_bounds__(256)
void scatter_ids_kernel(const int* __restrict__ src_idx) {
    __shared__ int sb[128];
    boff_scan(sb);
    const int t = blockIdx.x * blockDim.x + threadIdx.x;
    const int e = t * 4;
    if (e >= N_EDGES) return;
    const int4 s = *reinterpret_cast<const int4*>(src_idx + e);
    const int4 r = *reinterpret_cast<const int4*>(g_rank + e);
    g_eid[g_off[s.x] + sb[s.x >> 9] + r.x] = e;
    g_eid[g_off[s.y] + sb[s.y >> 9] + r.y] = e + 1;
    g_eid[g_off[s.z] + sb[s.z >> 9] + r.z] = e + 2;
    g_eid[g_off[s.w] + sb[s.w >> 9] + r.w] = e + 3;
}

// ---------------------------------------------------------------------------
// Kernel: gather-reduce (proven). One warp per node; 4 edge rows in flight.
// Runs ALONE — every fusion/overlap with it regressed (R7-R9, R13, R15).
// ---------------------------------------------------------------------------
__global__ __launch_bounds__(256)
void gather_kernel(const float* __restrict__ nbr_feat) {
    __shared__ int sb[128];
    boff_scan(sb);

    const int warp = (blockIdx.x * blockDim.x + threadIdx.x) >> 5;
    const int lane = threadIdx.x & 31;
    if (warp >= N_NODES) return;

    const int base = g_off[warp] + sb[warp >> 9];
    const int deg  = g_cnt_i[warp];

    const float4* nb4 = reinterpret_cast<const float4*>(nbr_feat);
    float4 acc = make_float4(0.f, 0.f, 0.f, 0.f);

    int i = 0;
    for (; i + 4 <= deg; i += 4) {
        const int e0 = g_eid[base + i];
        const int e1 = g_eid[base + i + 1];
        const int e2 = g_eid[base + i + 2];
        const int e3 = g_eid[base + i + 3];
        const float4 v0 = nb4[(size_t)e0 * (D_FEAT / 4) + lane];
        const float4 v1 = nb4[(size_t)e1 * (D_FEAT / 4) + lane];
        const float4 v2 = nb4[(size_t)e2 * (D_FEAT / 4) + lane];
        const float4 v3 = nb4[(size_t)e3 * (D_FEAT / 4) + lane];
        acc.x += (v0.x + v1.x) + (v2.x + v3.x);
        acc.y += (v0.y + v1.y) + (v2.y + v3.y);
        acc.z += (v0.z + v1.z) + (v2.z + v3.z);
        acc.w += (v0.w + v1.w) + (v2.w + v3.w);
    }
    for (; i < deg; ++i) {
        const int e = g_eid[base + i];
        const float4 v = nb4[(size_t)e * (D_FEAT / 4) + lane];
        acc.x += v.x; acc.y += v.y; acc.z += v.z; acc.w += v.w;
    }

    const float s = (deg > 0) ? (1.0f / (float)deg) : 0.0f;
    acc.x *= s; acc.y *= s; acc.z *= s; acc.w *= s;
    reinterpret_cast<float4*>(g_agg)[(size_t)warp * (D_FEAT / 4) + lane] = acc;
}

// ---------------------------------------------------------------------------
// cp.async helpers (base ISA, sm_80+)
// ---------------------------------------------------------------------------
__device__ __forceinline__ void cp16(uint32_t dst_smem, const void* src, int src_sz) {
    asm volatile("cp.async.cg.shared.global [%0], [%1], 16, %2;"
                 :: "r"(dst_smem), "l"(src), "r"(src_sz) : "memory");
}
__device__ __forceinline__ void cp_commit() {
    asm volatile("cp.async.commit_group;" ::: "memory");
}

// ---------------------------------------------------------------------------
// Kernel: fused concat + GEMM with cp.async double-buffered K-quarter fills.
// Inner FFMA2 loop is byte-identical to the proven R10/R14 version (frozen:
// smem-dup (R11) and 4x8 retile (R12) both regressed). K in 4 quarters of 64:
//   q0,q1: X = self_feat cols [0,64),[64,128); q2,q3: X = g_agg.
// smem: W[2][64][128] 64KB + X[2][64][64] 32KB = 96KB -> 2 CTAs/SM (same
// envelope as the 160.2us best). Quarter q+1's fill issues before quarter q's
// compute so fill latency hides under FMA.
// launch_bounds (256,2) = 128-reg budget (NEVER lower: (256,4) spilled, +50us).
// ---------------------------------------------------------------------------
#define BM   64
#define TPB  256
#define KQ   64
#define GEMM_SMEM ((2 * KQ * OUT_DIM + 2 * BM * KQ) * 4)   // 65536+32768 = 98304

__global__ __launch_bounds__(TPB, 2)
void gemm_kernel(const float* __restrict__ self_feat,
                 const float* __restrict__ W,
                 float*       __restrict__ out) {
    extern __shared__ float sh[];
    // Buffers: Wb[b] = sh + b*KQ*OUT_DIM ; Xb[b] = sh + 2*KQ*OUT_DIM + b*BM*KQ
    const int tid = threadIdx.x;
    const int n0  = blockIdx.x * BM;

    const uint32_t sh_u32 = (uint32_t)__cvta_generic_to_shared(sh);

    // Issue the fill for quarter q into buffer (q&1) via cp.async.
    auto issue_fill = [&](int q) {
        const int buf = q & 1;
        // W quarter: rows [q*KQ, q*KQ+64) -> 2048 float4, 8 per thread
        {
            const float4* Wsrc = reinterpret_cast<const float4*>(W + q * KQ * OUT_DIM);
            const uint32_t wdst = sh_u32 + (uint32_t)(buf * KQ * OUT_DIM * 4);
            #pragma unroll
            for (int i = tid; i < KQ * OUT_DIM / 4; i += TPB)
                cp16(wdst + i * 16, Wsrc + i, 16);
        }
        // X quarter: 64 rows x 16 float4; OOB rows zero-filled (src_sz=0)
        {
            const float* xsrc = (q < 2) ? self_feat : g_agg;
            const int    kofs = (q & 1) * KQ;
            const uint32_t xdst = sh_u32 +
                (uint32_t)((2 * KQ * OUT_DIM + buf * BM * KQ) * 4);
            #pragma unroll
            for (int i = tid; i < BM * (KQ / 4); i += TPB) {
                const int r  = i / (KQ / 4);
                const int c4 = i % (KQ / 4);
                const int n  = n0 + r;
                const float* src = xsrc + (size_t)n * D_FEAT + kofs + c4 * 4;
                const int sz = (n < N_NODES) ? 16 : 0;
                cp16(xdst + (uint32_t)((r * KQ + c4 * 4) * 4), src, sz);
            }
        }
    };

    const int j0 = (tid & 31) * 4;   // output column base
    const int r0 = (tid >> 5) * 8;   // row base within tile

    unsigned long long a01[8], a23[8];
    #pragma unroll
    for (int r = 0; r < 8; ++r) { a01[r] = 0ull; a23[r] = 0ull; }

    issue_fill(0);
    cp_commit();

    #pragma unroll
    for (int q = 0; q < 4; ++q) {
        if (q < 3) {
            issue_fill(q + 1);
            cp_commit();
            asm volatile("cp.async.wait_group 1;" ::: "memory");
        } else {
            asm volatile("cp.async.wait_group 0;" ::: "memory");
        }
        __syncthreads();

        const int buf = q & 1;
        const float* Wsh = sh + buf * KQ * OUT_DIM;
        const float* Xsh = sh + 2 * KQ * OUT_DIM + buf * BM * KQ;

        #pragma unroll 2
        for (int k = 0; k < KQ; k += 2) {
            const unsigned long long wA0 =
                *reinterpret_cast<const unsigned long long*>(&Wsh[k * OUT_DIM + j0]);
            const unsigned long long wB0 =
                *reinterpret_cast<const unsigned long long*>(&Wsh[k * OUT_DIM + j0 + 2]);
            const unsigned long long wA1 =
                *reinterpret_cast<const unsigned long long*>(&Wsh[(k + 1) * OUT_DIM + j0]);
            const unsigned long long wB1 =
                *reinterpret_cast<const unsigned long long*>(&Wsh[(k + 1) * OUT_DIM + j0 + 2]);

            #pragma unroll
            for (int r = 0; r < 8; ++r) {
                const float2 x = *reinterpret_cast<const float2*>(&Xsh[(r0 + r) * KQ + k]);
                unsigned long long xx0, xx1;
                asm("mov.b64 %0, {%1, %1};" : "=l"(xx0) : "f"(x.x));
                asm("mov.b64 %0, {%1, %1};" : "=l"(xx1) : "f"(x.y));
                asm("fma.rn.f32x2 %0, %1, %2, %0;" : "+l"(a01[r]) : "l"(xx0), "l"(wA0));
                asm("fma.rn.f32x2 %0, %1, %2, %0;" : "+l"(a23[r]) : "l"(xx0), "l"(wB0));
                asm("fma.rn.f32x2 %0, %1, %2, %0;" : "+l"(a01[r]) : "l"(xx1), "l"(wA1));
                asm("fma.rn.f32x2 %0, %1, %2, %0;" : "+l"(a23[r]) : "l"(xx1), "l"(wB1));
            }
        }
        __syncthreads();   // buffer safe to refill
    }

    #pragma unroll
    for (int r = 0; r < 8; ++r) {
        const int n = n0 + r0 + r;
        if (n < N_NODES) {
            float o0, o1, o2, o3;
            asm("mov.b64 {%0, %1}, %2;" : "=f"(o0), "=f"(o1) : "l"(a01[r]));
            asm("mov.b64 {%0, %1}, %2;" : "=f"(o2), "=f"(o3) : "l"(a23[r]));
            *reinterpret_cast<float4*>(&out[(size_t)n * OUT_DIM + j0]) =
                make_float4(o0, o1, o2, o3);
        }
    }
}

// ---------------------------------------------------------------------------
// Launch — 6 kernels, strictly serial (every overlap/fusion variant lost).
// ---------------------------------------------------------------------------
extern "C" void kernel_launch(void* const* d_in, const int* in_sizes, int n_in,
                              void* d_out, int out_size) {
    const float* self_feat = (const float*)d_in[0];
    const float* nbr_feat  = (const float*)d_in[1];
    const int*   src_idx   = (const int*)  d_in[2];
    const float* W         = (const float*)d_in[3];
    float*       out       = (float*)d_out;

    (void)in_sizes; (void)n_in; (void)out_size;

    const int nodes_blks = (N_NODES + 255) / 256;
    const int e4_blks    = (N_EDGES / 4 + 255) / 256;

    zero_counters_kernel<<<nodes_blks, 256>>>();           // 1
    count_rank_kernel<<<e4_blks, 256>>>(src_idx);          // 2
    scan_partial_kernel<<<N_SCAN_BLKS, SCAN_BLK>>>();      // 3
    scatter_ids_kernel<<<e4_blks, 256>>>(src_idx);         // 4
    gather_kernel<<<(N_NODES + 7) / 8, 256>>>(nbr_feat);   // 5

    cudaFuncSetAttribute(gemm_kernel,
                         cudaFuncAttributeMaxDynamicSharedMemorySize, GEMM_SMEM);
    gemm_kernel<<<(N_NODES + BM - 1) / BM, TPB, GEMM_SMEM>>>(self_feat, W, out);  // 6
}

// round 17
// speedup vs baseline: 1.1644x; 1.0352x over previous
#include <cuda_runtime.h>
#include <cuda_bf16.h>
#include <cstdint>

#define N_NODES 50000
#define N_EDGES 600000
#define D_FEAT  128
#define OUT_DIM 128
#define K_DIM   256

#define SCAN_BLK 512
#define N_SCAN_BLKS ((N_NODES + SCAN_BLK - 1) / SCAN_BLK)   // 98

// ---------------------------------------------------------------------------
// Scratch (static device globals)
// ---------------------------------------------------------------------------
__device__ int g_cnt_i [N_NODES];
__device__ int g_off   [N_NODES];
__device__ int g_btot  [N_SCAN_BLKS];
__device__ __align__(16) int g_rank[N_EDGES];
__device__ int g_eid   [N_EDGES];
__device__ __align__(16) float g_agg[N_NODES * D_FEAT];   // 25.6 MB

// ---------------------------------------------------------------------------
// Kernel: zero counters
// ---------------------------------------------------------------------------
__global__ void zero_counters_kernel() {
    int i = blockIdx.x * blockDim.x + threadIdx.x;
    if (i < N_NODES) g_cnt_i[i] = 0;
}

// ---------------------------------------------------------------------------
// Kernel: histogram + per-edge rank, 2 edges per thread (x4 in R14 halved
// occupancy and was neutral; x2 keeps 2 chains in flight at 2x the blocks)
// ---------------------------------------------------------------------------
__global__ void count_rank_kernel(const int* __restrict__ src_idx) {
    const int t = blockIdx.x * blockDim.x + threadIdx.x;
    const int e = t * 2;
    if (e >= N_EDGES) return;
    const int2 s = *reinterpret_cast<const int2*>(src_idx + e);
    int2 r;
    r.x = atomicAdd(&g_cnt_i[s.x], 1);
    r.y = atomicAdd(&g_cnt_i[s.y], 1);
    *reinterpret_cast<int2*>(g_rank + e) = r;
}

// ---------------------------------------------------------------------------
// Kernel: per-block exclusive scan (warp-shuffle)
// ---------------------------------------------------------------------------
__global__ __launch_bounds__(SCAN_BLK)
void scan_partial_kernel() {
    __shared__ int wtot[16];
    const int tid  = threadIdx.x;
    const int lane = tid & 31;
    const int wid  = tid >> 5;
    const int i    = blockIdx.x * SCAN_BLK + tid;
    const int v    = (i < N_NODES) ? g_cnt_i[i] : 0;

    int x = v;
    #pragma unroll
    for (int d = 1; d < 32; d <<= 1) {
        int y = __shfl_up_sync(0xffffffffu, x, d);
        if (lane >= d) x += y;
    }
    if (lane == 31) wtot[wid] = x;
    __syncthreads();

    if (wid == 0) {
        int w = (lane < 16) ? wtot[lane] : 0;
        int ws = w;
        #pragma unroll
        for (int d = 1; d < 16; d <<= 1) {
            int y = __shfl_up_sync(0xffffffffu, ws, d);
            if (lane >= d) ws += y;
        }
        if (lane < 16) wtot[lane] = ws - w;
    }
    __syncthreads();

    const int incl = x + wtot[wid];
    if (i < N_NODES) g_off[i] = incl - v;
    if (tid == SCAN_BLK - 1) g_btot[blockIdx.x] = incl;
}

// ---------------------------------------------------------------------------
// Inline 98-element exclusive prefix of g_btot. All threads join.
// ---------------------------------------------------------------------------
__device__ __forceinline__ void boff_scan(int* sb) {
    const int tid = threadIdx.x;
    int v = 0;
    if (tid < 128) {
        v = (tid < N_SCAN_BLKS) ? g_btot[tid] : 0;
        sb[tid] = v;
    }
    __syncthreads();
    #pragma unroll
    for (int d = 1; d < 128; d <<= 1) {
        int x = (tid < 128 && tid >= d) ? sb[tid - d] : 0;
        __syncthreads();
        if (tid < 128) sb[tid] += x;
        __syncthreads();
    }
    if (tid < 128) sb[tid] -= v;
    __syncthreads();
}

// ---------------------------------------------------------------------------
// Kernel: scatter edge ids — atomic-free, 2 edges per thread
// ---------------------------------------------------------------------------
__global__ __launch_bounds__(256)
void scatter_ids_kernel(const int* __restrict__ src_idx) {
    __shared__ int sb[128];
    boff_scan(sb);
    const int t = blockIdx.x * blockDim.x + threadIdx.x;
    const int e = t * 2;
    if (e >= N_EDGES) return;
    const int2 s = *reinterpret_cast<const int2*>(src_idx + e);
    const int2 r = *reinterpret_cast<const int2*>(g_rank + e);
    g_eid[g_off[s.x] + sb[s.x >> 9] + r.x] = e;
    g_eid[g_off[s.y] + sb[s.y >> 9] + r.y] = e + 1;
}

// ---------------------------------------------------------------------------
// Kernel: gather-reduce. One warp per node; 4 edge rows in flight; streaming
// loads (__ldcs — zero reuse, keep L1/L2 for metadata). deg%4 tail handled
// inside one predicated batch (index-clamped) instead of a serial loop.
// Runs ALONE — every fusion/overlap with it regressed (R7-R9, R13, R15).
// ---------------------------------------------------------------------------
__global__ __launch_bounds__(256)
void gather_kernel(const float* __restrict__ nbr_feat) {
    __shared__ int sb[128];
    boff_scan(sb);

    const int warp = (blockIdx.x * blockDim.x + threadIdx.x) >> 5;
    const int lane = threadIdx.x & 31;
    if (warp >= N_NODES) return;

    const int base = g_off[warp] + sb[warp >> 9];
    const int deg  = g_cnt_i[warp];

    const float4* nb4 = reinterpret_cast<const float4*>(nbr_feat);
    float4 acc = make_float4(0.f, 0.f, 0.f, 0.f);

    for (int i = 0; i < deg; i += 4) {
        // Clamp indices into the valid range; zero out-of-range contributions.
        const int i1 = (i + 1 < deg) ? i + 1 : i;
        const int i2 = (i + 2 < deg) ? i + 2 : i;
        const int i3 = (i + 3 < deg) ? i + 3 : i;
        const int e0 = g_eid[base + i];
        const int e1 = g_eid[base + i1];
        const int e2 = g_eid[base + i2];
        const int e3 = g_eid[base + i3];
        const float4 v0 = __ldcs(&nb4[(size_t)e0 * (D_FEAT / 4) + lane]);
        float4 v1 = __ldcs(&nb4[(size_t)e1 * (D_FEAT / 4) + lane]);
        float4 v2 = __ldcs(&nb4[(size_t)e2 * (D_FEAT / 4) + lane]);
        float4 v3 = __ldcs(&nb4[(size_t)e3 * (D_FEAT / 4) + lane]);
        if (i + 1 >= deg) { v1.x = v1.y = v1.z = v1.w = 0.f; }
        if (i + 2 >= deg) { v2.x = v2.y = v2.z = v2.w = 0.f; }
        if (i + 3 >= deg) { v3.x = v3.y = v3.z = v3.w = 0.f; }
        acc.x += (v0.x + v1.x) + (v2.x + v3.x);
        acc.y += (v0.y + v1.y) + (v2.y + v3.y);
        acc.z += (v0.z + v1.z) + (v2.z + v3.z);
        acc.w += (v0.w + v1.w) + (v2.w + v3.w);
    }

    const float s = (deg > 0) ? (1.0f / (float)deg) : 0.0f;
    acc.x *= s; acc.y *= s; acc.z *= s; acc.w *= s;
    reinterpret_cast<float4*>(g_agg)[(size_t)warp * (D_FEAT / 4) + lane] = acc;
}

// ---------------------------------------------------------------------------
// cp.async helpers (base ISA, sm_80+)
// ---------------------------------------------------------------------------
__device__ __forceinline__ void cp16(uint32_t dst_smem, const void* src, int src_sz) {
    asm volatile("cp.async.cg.shared.global [%0], [%1], 16, %2;"
                 :: "r"(dst_smem), "l"(src), "r"(src_sz) : "memory");
}
__device__ __forceinline__ void cp_commit() {
    asm volatile("cp.async.commit_group;" ::: "memory");
}

// ---------------------------------------------------------------------------
// Kernel: fused concat + GEMM with cp.async double-buffered K-quarter fills
// (R16-proven winner — FROZEN: inner loop jointly FFMA2-issue and smem-
// crossbar bound; R11/R12 variants both regressed).
// launch_bounds (256,2) = 128-reg budget (NEVER lower: (256,4) spilled, +50us).
// ---------------------------------------------------------------------------
#define BM   64
#define TPB  256
#define KQ   64
#define GEMM_SMEM ((2 * KQ * OUT_DIM + 2 * BM * KQ) * 4)   // 98304

__global__ __launch_bounds__(TPB, 2)
void gemm_kernel(const float* __restrict__ self_feat,
                 const float* __restrict__ W,
                 float*       __restrict__ out) {
    extern __shared__ float sh[];
    const int tid = threadIdx.x;
    const int n0  = blockIdx.x * BM;

    const uint32_t sh_u32 = (uint32_t)__cvta_generic_to_shared(sh);

    auto issue_fill = [&](int q) {
        const int buf = q & 1;
        {
            const float4* Wsrc = reinterpret_cast<const float4*>(W + q * KQ * OUT_DIM);
            const uint32_t wdst = sh_u32 + (uint32_t)(buf * KQ * OUT_DIM * 4);
            #pragma unroll
            for (int i = tid; i < KQ * OUT_DIM / 4; i += TPB)
                cp16(wdst + i * 16, Wsrc + i, 16);
        }
        {
            const float* xsrc = (q < 2) ? self_feat : g_agg;
            const int    kofs = (q & 1) * KQ;
            const uint32_t xdst = sh_u32 +
                (uint32_t)((2 * KQ * OUT_DIM + buf * BM * KQ) * 4);
            #pragma unroll
            for (int i = tid; i < BM * (KQ / 4); i += TPB) {
                const int r  = i / (KQ / 4);
                const int c4 = i % (KQ / 4);
                const int n  = n0 + r;
                const float* src = xsrc + (size_t)n * D_FEAT + kofs + c4 * 4;
                const int sz = (n < N_NODES) ? 16 : 0;
                cp16(xdst + (uint32_t)((r * KQ + c4 * 4) * 4), src, sz);
            }
        }
    };

    const int j0 = (tid & 31) * 4;
    const int r0 = (tid >> 5) * 8;

    unsigned long long a01[8], a23[8];
    #pragma unroll
    for (int r = 0; r < 8; ++r) { a01[r] = 0ull; a23[r] = 0ull; }

    issue_fill(0);
    cp_commit();

    #pragma unroll
    for (int q = 0; q < 4; ++q) {
        if (q < 3) {
            issue_fill(q + 1);
            cp_commit();
            asm volatile("cp.async.wait_group 1;" ::: "memory");
        } else {
            asm volatile("cp.async.wait_group 0;" ::: "memory");
        }
        __syncthreads();

        const int buf = q & 1;
        const float* Wsh = sh + buf * KQ * OUT_DIM;
        const float* Xsh = sh + 2 * KQ * OUT_DIM + buf * BM * KQ;

        #pragma unroll 2
        for (int k = 0; k < KQ; k += 2) {
            const unsigned long long wA0 =
                *reinterpret_cast<const unsigned long long*>(&Wsh[k * OUT_DIM + j0]);
            const unsigned long long wB0 =
                *reinterpret_cast<const unsigned long long*>(&Wsh[k * OUT_DIM + j0 + 2]);
            const unsigned long long wA1 =
                *reinterpret_cast<const unsigned long long*>(&Wsh[(k + 1) * OUT_DIM + j0]);
            const unsigned long long wB1 =
                *reinterpret_cast<const unsigned long long*>(&Wsh[(k + 1) * OUT_DIM + j0 + 2]);

            #pragma unroll
            for (int r = 0; r < 8; ++r) {
                const float2 x = *reinterpret_cast<const float2*>(&Xsh[(r0 + r) * KQ + k]);
                unsigned long long xx0, xx1;
                asm("mov.b64 %0, {%1, %1};" : "=l"(xx0) : "f"(x.x));
                asm("mov.b64 %0, {%1, %1};" : "=l"(xx1) : "f"(x.y));
                asm("fma.rn.f32x2 %0, %1, %2, %0;" : "+l"(a01[r]) : "l"(xx0), "l"(wA0));
                asm("fma.rn.f32x2 %0, %1, %2, %0;" : "+l"(a23[r]) : "l"(xx0), "l"(wB0));
                asm("fma.rn.f32x2 %0, %1, %2, %0;" : "+l"(a01[r]) : "l"(xx1), "l"(wA1));
                asm("fma.rn.f32x2 %0, %1, %2, %0;" : "+l"(a23[r]) : "l"(xx1), "l"(wB1));
            }
        }
        __syncthreads();
    }

    #pragma unroll
    for (int r = 0; r < 8; ++r) {
        const int n = n0 + r0 + r;
        if (n < N_NODES) {
            float o0, o1, o2, o3;
            asm("mov.b64 {%0, %1}, %2;" : "=f"(o0), "=f"(o1) : "l"(a01[r]));
            asm("mov.b64 {%0, %1}, %2;" : "=f"(o2), "=f"(o3) : "l"(a23[r]));
            *reinterpret_cast<float4*>(&out[(size_t)n * OUT_DIM + j0]) =
                make_float4(o0, o1, o2, o3);
        }
    }
}

// ---------------------------------------------------------------------------
// Launch — 6 kernels, strictly serial (every overlap/fusion variant lost).
// ---------------------------------------------------------------------------
extern "C" void kernel_launch(void* const* d_in, const int* in_sizes, int n_in,
                              void* d_out, int out_size) {
    const float* self_feat = (const float*)d_in[0];
    const float* nbr_feat  = (const float*)d_in[1];
    const int*   src_idx   = (const int*)  d_in[2];
    const float* W         = (const float*)d_in[3];
    float*       out       = (float*)d_out;

    (void)in_sizes; (void)n_in; (void)out_size;

    const int nodes_blks = (N_NODES + 255) / 256;
    const int e2_blks    = (N_EDGES / 2 + 255) / 256;

    zero_counters_kernel<<<nodes_blks, 256>>>();           // 1
    count_rank_kernel<<<e2_blks, 256>>>(src_idx);          // 2
    scan_partial_kernel<<<N_SCAN_BLKS, SCAN_BLK>>>();      // 3
    scatter_ids_kernel<<<e2_blks, 256>>>(src_idx);         // 4
    gather_kernel<<<(N_NODES + 7) / 8, 256>>>(nbr_feat);   // 5

    cudaFuncSetAttribute(gemm_kernel,
                         cudaFuncAttributeMaxDynamicSharedMemorySize, GEMM_SMEM);
    gemm_kernel<<<(N_NODES + BM - 1) / BM, TPB, GEMM_SMEM>>>(self_feat, W, out);  // 6
}